// round 14
// baseline (speedup 1.0000x reference)
#include <cuda_runtime.h>
#include <cuda_bf16.h>
#include <math.h>
#include <stdint.h>

#define NROWS 100000
#define MTRIP 800000
#define HID   128
#define HEADS 8
#define NBLK  ((NROWS + 1023) / 1024)

// packed bf16-pair words per row: 64 + pad. 68 => (g*4+tg) distinct mod 32
#define PAD2  68
// smem: As_hi, As_lo (64 rows) + Ws_hi, Ws_lo (128 rows), uint32 words
#define GEMM_SMEM ((64 * 2 + 128 * 2) * PAD2 * 4)

// ---------------- scratch (static device globals; no allocs allowed) ----------------
__device__ float g_q[NROWS * HID];
__device__ float g_k[NROWS * HID];
__device__ float g_v[NROWS * HID];
__device__ float g_agg[NROWS * HID];
__device__ int   g_hist[NROWS + 1];   // exclusive segment offsets after scan
__device__ int   g_cursor[NROWS];
__device__ int   g_bsums[NBLK];
__device__ int   g_perm[MTRIP];       // stores source index kj, dest-sorted
__device__ int   g_is64;

// ---------------- index dtype detection ----------------
__global__ void detect_kernel(const unsigned int* raw, int m) {
    __shared__ int nz;
    if (threadIdx.x == 0) nz = 0;
    __syncthreads();
    int c = m < 2048 ? m : 2048;
    int local = 0;
    for (int i = threadIdx.x; i < c; i += blockDim.x)
        if (raw[2 * i + 1] != 0u) local = 1;
    if (local) atomicOr(&nz, 1);
    __syncthreads();
    if (threadIdx.x == 0) g_is64 = (nz == 0) ? 1 : 0;
}

__device__ __forceinline__ long long load_idx(const void* p, int i, bool is64) {
    return is64 ? ((const long long*)p)[i] : (long long)((const int*)p)[i];
}

// ---------------- counting sort by destination (idx_ji) ----------------
__global__ void zero_hist() {
    for (int i = blockIdx.x * blockDim.x + threadIdx.x; i <= NROWS;
         i += gridDim.x * blockDim.x)
        g_hist[i] = 0;
}

__global__ void hist_kernel(const void* __restrict__ idx_ji, int m) {
    bool is64 = (g_is64 != 0);
    for (int e = blockIdx.x * blockDim.x + threadIdx.x; e < m;
         e += gridDim.x * blockDim.x)
        atomicAdd(&g_hist[(int)load_idx(idx_ji, e, is64)], 1);
}

__global__ void scan1_kernel() {
    __shared__ int s[1024];
    int t = threadIdx.x;
    int i = blockIdx.x * 1024 + t;
    int v = (i < NROWS) ? g_hist[i] : 0;
    s[t] = v;
    __syncthreads();
#pragma unroll
    for (int off = 1; off < 1024; off <<= 1) {
        int x = (t >= off) ? s[t - off] : 0;
        __syncthreads();
        s[t] += x;
        __syncthreads();
    }
    if (i < NROWS) g_hist[i] = s[t] - v;   // exclusive within block
    if (t == 1023) g_bsums[blockIdx.x] = s[t];
}

__global__ void scan2_kernel() {
    int running = 0;
    for (int b = 0; b < NBLK; ++b) {
        int t = g_bsums[b];
        g_bsums[b] = running;
        running += t;
    }
    g_hist[NROWS] = running;   // = M
}

__global__ void scan3_kernel() {
    for (int i = blockIdx.x * blockDim.x + threadIdx.x; i < NROWS;
         i += gridDim.x * blockDim.x) {
        int v = g_hist[i] + g_bsums[i >> 10];
        g_hist[i] = v;
        g_cursor[i] = v;
    }
}

// scatter the SOURCE index (kj) into destination-sorted order
__global__ void scatter_kernel(const void* __restrict__ idx_ji,
                               const void* __restrict__ idx_kj, int m) {
    bool is64 = (g_is64 != 0);
    for (int e = blockIdx.x * blockDim.x + threadIdx.x; e < m;
         e += gridDim.x * blockDim.x) {
        int d = (int)load_idx(idx_ji, e, is64);
        int src = (int)load_idx(idx_kj, e, is64);
        int pos = atomicAdd(&g_cursor[d], 1);
        g_perm[pos] = src;
    }
}

// ================== bf16x2 3-term GEMM via mma.sync.m16n8k16 =======================
__device__ __forceinline__ void split_pack(float v0, float v1,
                                           uint32_t& hi, uint32_t& lo) {
    __nv_bfloat162 h2 = __floats2bfloat162_rn(v0, v1);
    hi = *reinterpret_cast<uint32_t*>(&h2);
    float r0 = v0 - __bfloat162float(h2.x);
    float r1 = v1 - __bfloat162float(h2.y);
    __nv_bfloat162 l2 = __floats2bfloat162_rn(r0, r1);
    lo = *reinterpret_cast<uint32_t*>(&l2);
}

__device__ __forceinline__ void mma16(float c[4], const uint32_t a[4],
                                      const uint32_t b[2]) {
    asm volatile(
        "mma.sync.aligned.m16n8k16.row.col.f32.bf16.bf16.f32 "
        "{%0,%1,%2,%3}, {%4,%5,%6,%7}, {%8,%9}, {%0,%1,%2,%3};"
        : "+f"(c[0]), "+f"(c[1]), "+f"(c[2]), "+f"(c[3])
        : "r"(a[0]), "r"(a[1]), "r"(a[2]), "r"(a[3]), "r"(b[0]), "r"(b[1]));
}

// Core: stages W split into SMEM, runs 8 k16-steps of bf16x2 3-term MMA.
// mode 0: write out rows (optional bias/relu/addsrc)
// mode 1: write relu(x + bias) back into As_hi/As_lo (for fused MLP middle layer)
__device__ __noinline__ void gemm_core(uint32_t* As_hi, uint32_t* As_lo,
                                       uint32_t* Ws_hi, uint32_t* Ws_lo,
                                       const float* __restrict__ W,
                                       const float* __restrict__ bias,
                                       const float* __restrict__ addsrc,
                                       float* __restrict__ out,
                                       int nrows, int row0, int dorelu, int mode) {
    const int tid = threadIdx.x;
    const int lane = tid & 31;
    const int wid = tid >> 5;
    const int wm = wid & 1, wn = wid >> 1;   // warp tile 32x32
    const int g = lane >> 2, tg = lane & 3;

    __syncthreads();   // previous consumers of Ws / As writers done
    // stage W: 128 rows x 64 pairs = 8192 words
#pragma unroll
    for (int it = 0; it < 32; ++it) {
        int e = tid + it * 256;
        int o = e >> 6, p = e & 63;
        float2 w = ((const float2*)W)[e];
        uint32_t h, l;
        split_pack(w.x, w.y, h, l);
        Ws_hi[o * PAD2 + p] = h;
        Ws_lo[o * PAD2 + p] = l;
    }
    __syncthreads();

    float acc[2][4][4];
#pragma unroll
    for (int i = 0; i < 2; ++i)
#pragma unroll
        for (int j = 0; j < 4; ++j)
#pragma unroll
            for (int q = 0; q < 4; ++q) acc[i][j][q] = 0.f;

#pragma unroll
    for (int ks = 0; ks < 8; ++ks) {
        const int kp = ks * 8;
        uint32_t ah[2][4], al[2][4], bh[4][2], bl[4][2];
#pragma unroll
        for (int mf = 0; mf < 2; ++mf) {
            int br = wm * 32 + mf * 16;
            ah[mf][0] = As_hi[(br + g) * PAD2 + kp + tg];
            ah[mf][1] = As_hi[(br + g + 8) * PAD2 + kp + tg];
            ah[mf][2] = As_hi[(br + g) * PAD2 + kp + tg + 4];
            ah[mf][3] = As_hi[(br + g + 8) * PAD2 + kp + tg + 4];
            al[mf][0] = As_lo[(br + g) * PAD2 + kp + tg];
            al[mf][1] = As_lo[(br + g + 8) * PAD2 + kp + tg];
            al[mf][2] = As_lo[(br + g) * PAD2 + kp + tg + 4];
            al[mf][3] = As_lo[(br + g + 8) * PAD2 + kp + tg + 4];
        }
#pragma unroll
        for (int nf = 0; nf < 4; ++nf) {
            int col = wn * 32 + nf * 8 + g;
            bh[nf][0] = Ws_hi[col * PAD2 + kp + tg];
            bh[nf][1] = Ws_hi[col * PAD2 + kp + tg + 4];
            bl[nf][0] = Ws_lo[col * PAD2 + kp + tg];
            bl[nf][1] = Ws_lo[col * PAD2 + kp + tg + 4];
        }
#pragma unroll
        for (int mf = 0; mf < 2; ++mf)
#pragma unroll
            for (int nf = 0; nf < 4; ++nf) {
                mma16(acc[mf][nf], ah[mf], bh[nf]);
                mma16(acc[mf][nf], ah[mf], bl[nf]);
                mma16(acc[mf][nf], al[mf], bh[nf]);
            }
    }

    if (mode == 1) {
        // fused-MLP middle layer: h = relu(x + bias) -> back into As (split bf16)
        __syncthreads();   // all warps done reading As
#pragma unroll
        for (int mf = 0; mf < 2; ++mf) {
#pragma unroll
            for (int half = 0; half < 2; ++half) {
                int rl = wm * 32 + mf * 16 + g + half * 8;
#pragma unroll
                for (int nf = 0; nf < 4; ++nf) {
                    int col = wn * 32 + nf * 8 + 2 * tg;
                    float x = fmaxf(acc[mf][nf][half * 2 + 0] + bias[col], 0.f);
                    float y = fmaxf(acc[mf][nf][half * 2 + 1] + bias[col + 1], 0.f);
                    uint32_t h, l;
                    split_pack(x, y, h, l);
                    int widx = rl * PAD2 + wn * 16 + nf * 4 + tg;
                    As_hi[widx] = h;
                    As_lo[widx] = l;
                }
            }
        }
        return;   // caller's next gemm_core starts with __syncthreads()
    }

    // epilogue to gmem
#pragma unroll
    for (int mf = 0; mf < 2; ++mf) {
#pragma unroll
        for (int half = 0; half < 2; ++half) {
            int r = row0 + wm * 32 + mf * 16 + g + half * 8;
            if (r >= nrows) continue;
#pragma unroll
            for (int nf = 0; nf < 4; ++nf) {
                int col = wn * 32 + nf * 8 + 2 * tg;
                float x = acc[mf][nf][half * 2 + 0];
                float y = acc[mf][nf][half * 2 + 1];
                if (bias) { x += bias[col]; y += bias[col + 1]; }
                if (dorelu) { x = fmaxf(x, 0.f); y = fmaxf(y, 0.f); }
                if (addsrc) {
                    const float* ap = addsrc + (size_t)r * HID + col;
                    x += ap[0]; y += ap[1];
                }
                *(float2*)(out + (size_t)r * HID + col) = make_float2(x, y);
            }
        }
    }
}

// ---- stage 64-row fp32 A tile into SMEM as split bf16 pairs ----
__device__ __forceinline__ void stage_A(uint32_t* As_hi, uint32_t* As_lo,
                                        const float* __restrict__ A,
                                        int nrows, int row0) {
    const int tid = threadIdx.x;
#pragma unroll
    for (int it = 0; it < 16; ++it) {
        int e = tid + it * 256;       // 64 rows x 64 pairs = 4096 words
        int r = e >> 6, p = e & 63;
        float2 a = make_float2(0.f, 0.f);
        if (row0 + r < nrows)
            a = ((const float2*)(A + (size_t)(row0 + r) * HID))[p];
        uint32_t h, l;
        split_pack(a.x, a.y, h, l);
        As_hi[r * PAD2 + p] = h;
        As_lo[r * PAD2 + p] = l;
    }
}

// ---- fused Q/K/V projection ----
__global__ __launch_bounds__(256, 2)
void gemm_qkv(const float* __restrict__ feats, const float* __restrict__ Wq,
              const float* __restrict__ Wk, const float* __restrict__ Wv,
              float* __restrict__ q, float* __restrict__ k, float* __restrict__ v,
              int nrows) {
    extern __shared__ uint32_t smem_u[];
    uint32_t* As_hi = smem_u;
    uint32_t* As_lo = As_hi + 64 * PAD2;
    uint32_t* Ws_hi = As_lo + 64 * PAD2;
    uint32_t* Ws_lo = Ws_hi + 128 * PAD2;
    int row0 = blockIdx.x * 64;
    stage_A(As_hi, As_lo, feats, nrows, row0);
    gemm_core(As_hi, As_lo, Ws_hi, Ws_lo, Wq, nullptr, nullptr, q, nrows, row0, 0, 0);
    gemm_core(As_hi, As_lo, Ws_hi, Ws_lo, Wk, nullptr, nullptr, k, nrows, row0, 0, 0);
    gemm_core(As_hi, As_lo, Ws_hi, Ws_lo, Wv, nullptr, nullptr, v, nrows, row0, 0, 0);
}

// ---- fused MLP: out = v + relu(W2 @ relu(W1 @ agg + b1) + b2) ----
__global__ __launch_bounds__(256, 2)
void gemm_mlp(const float* __restrict__ W1, const float* __restrict__ b1,
              const float* __restrict__ W2, const float* __restrict__ b2,
              const float* __restrict__ v, float* __restrict__ out, int nrows) {
    extern __shared__ uint32_t smem_u[];
    uint32_t* As_hi = smem_u;
    uint32_t* As_lo = As_hi + 64 * PAD2;
    uint32_t* Ws_hi = As_lo + 64 * PAD2;
    uint32_t* Ws_lo = Ws_hi + 128 * PAD2;
    int row0 = blockIdx.x * 64;
    stage_A(As_hi, As_lo, g_agg, nrows, row0);
    gemm_core(As_hi, As_lo, Ws_hi, Ws_lo, W1, b1, nullptr, nullptr, nrows, row0, 1, 1);
    gemm_core(As_hi, As_lo, Ws_hi, Ws_lo, W2, b2, v, out, nrows, row0, 1, 0);
}

// ---- fused attention + aggregation, warp per node, 2-stage software pipeline ------
// Pair loads for iteration i+1 issue at the top of iteration i (branch-free via
// index clamp to row 0 and zeroed weights), giving each L2 gather a full
// iteration of slack instead of stalling at point of use.
__global__ void att_agg_kernel() {
    int n = (blockIdx.x * blockDim.x + threadIdx.x) >> 5;
    if (n >= NROWS) return;
    int lane = threadIdx.x & 31;
    const float4* Q4 = (const float4*)g_q;
    const float4* V4 = (const float4*)g_v;

    int start = g_hist[n], end = g_hist[n + 1];
    float4 kv = ((const float4*)g_k)[(size_t)n * 32 + lane];
    float4 acc = make_float4(0.f, 0.f, 0.f, 0.f);
    float denom = 0.f;

    if (start < end) {
        // prologue: load pair 0 (clamped)
        int p = start;
        int kj0 = __ldg(&g_perm[p]);
        int kj1 = (p + 1 < end) ? __ldg(&g_perm[p + 1]) : 0;
        float4 q0 = Q4[(size_t)kj0 * 32 + lane];
        float4 v0 = V4[(size_t)kj0 * 32 + lane];
        float4 q1 = Q4[(size_t)kj1 * 32 + lane];
        float4 v1 = V4[(size_t)kj1 * 32 + lane];

        while (p < end) {
            // issue next pair's loads (clamped to row 0; weights zeroed later)
            int np = p + 2;
            int nk0 = (np < end) ? __ldg(&g_perm[np]) : 0;
            int nk1 = (np + 1 < end) ? __ldg(&g_perm[np + 1]) : 0;
            float4 nq0 = Q4[(size_t)nk0 * 32 + lane];
            float4 nv0 = V4[(size_t)nk0 * 32 + lane];
            float4 nq1 = Q4[(size_t)nk1 * 32 + lane];
            float4 nv1 = V4[(size_t)nk1 * 32 + lane];

            // compute current pair
            float d0 = q0.x * kv.x + q0.y * kv.y + q0.z * kv.z + q0.w * kv.w;
            float d1 = q1.x * kv.x + q1.y * kv.y + q1.z * kv.z + q1.w * kv.w;
            d0 += __shfl_xor_sync(0xffffffffu, d0, 1);
            d1 += __shfl_xor_sync(0xffffffffu, d1, 1);
            d0 += __shfl_xor_sync(0xffffffffu, d0, 2);
            d1 += __shfl_xor_sync(0xffffffffu, d1, 2);
            float s0 = d0 > 0.f ? d0 : 0.2f * d0;
            float s1 = d1 > 0.f ? d1 : 0.2f * d1;
            float a0 = __expf(s0);                       // p < end always
            float a1 = (p + 1 < end) ? __expf(s1) : 0.f; // zero-weight padding
            denom += a0 + a1;
            acc.x += a0 * v0.x + a1 * v1.x;
            acc.y += a0 * v0.y + a1 * v1.y;
            acc.z += a0 * v0.z + a1 * v1.z;
            acc.w += a0 * v0.w + a1 * v1.w;

            // rotate pipeline
            q0 = nq0; v0 = nv0; q1 = nq1; v1 = nv1;
            p = np;
        }
    }

    float inv = (end > start) ? 1.f / denom : 0.f;
    float4 o = make_float4(acc.x * inv, acc.y * inv, acc.z * inv, acc.w * inv);
    ((float4*)g_agg)[(size_t)n * 32 + lane] = o;
}

// ---------------- launch ----------------
extern "C" void kernel_launch(void* const* d_in, const int* in_sizes, int n_in,
                              void* d_out, int out_size) {
    const float* feats = (const float*)d_in[0];
    const void*  idx_kj = d_in[1];
    const void*  idx_ji = d_in[2];
    const float* Wv = (const float*)d_in[3];
    const float* Wq = (const float*)d_in[4];
    const float* Wk = (const float*)d_in[5];
    const float* W1 = (const float*)d_in[6];
    const float* b1 = (const float*)d_in[7];
    const float* W2 = (const float*)d_in[8];
    const float* b2 = (const float*)d_in[9];
    float* out = (float*)d_out;

    int nrows = in_sizes[0] / HID;
    int m     = in_sizes[1];

    float *q_p, *k_p, *v_p;
    cudaGetSymbolAddress((void**)&q_p, g_q);
    cudaGetSymbolAddress((void**)&k_p, g_k);
    cudaGetSymbolAddress((void**)&v_p, g_v);

    cudaFuncSetAttribute(gemm_qkv, cudaFuncAttributeMaxDynamicSharedMemorySize,
                         GEMM_SMEM);
    cudaFuncSetAttribute(gemm_mlp, cudaFuncAttributeMaxDynamicSharedMemorySize,
                         GEMM_SMEM);

    // side stream + events for overlapping the sort chain with gemm_qkv
    static cudaStream_t s_side = nullptr;
    static cudaEvent_t  ev_fork = nullptr, ev_join = nullptr;
    if (!s_side) {
        cudaStreamCreateWithFlags(&s_side, cudaStreamNonBlocking);
        cudaEventCreateWithFlags(&ev_fork, cudaEventDisableTiming);
        cudaEventCreateWithFlags(&ev_join, cudaEventDisableTiming);
    }

    // fork: sort triplets by destination on the side stream (overlaps gemm_qkv)
    cudaEventRecord(ev_fork, 0);
    cudaStreamWaitEvent(s_side, ev_fork, 0);
    detect_kernel<<<1, 256, 0, s_side>>>((const unsigned int*)idx_kj, m);
    zero_hist<<<256, 256, 0, s_side>>>();
    hist_kernel<<<1024, 256, 0, s_side>>>(idx_ji, m);
    scan1_kernel<<<NBLK, 1024, 0, s_side>>>();
    scan2_kernel<<<1, 1, 0, s_side>>>();
    scan3_kernel<<<256, 256, 0, s_side>>>();
    scatter_kernel<<<1024, 256, 0, s_side>>>(idx_ji, idx_kj, m);
    cudaEventRecord(ev_join, s_side);

    // main stream: QKV projections (independent of the sort)
    int gblocks = (nrows + 63) / 64;
    gemm_qkv<<<gblocks, 256, GEMM_SMEM>>>(feats, Wq, Wk, Wv, q_p, k_p, v_p, nrows);

    // join sort, then attention + fused MLP
    cudaStreamWaitEvent(0, ev_join, 0);
    int ablocks = (NROWS * 32 + 255) / 256;
    att_agg_kernel<<<ablocks, 256>>>();

    gemm_mlp<<<gblocks, 256, GEMM_SMEM>>>(W1, b1, W2, b2, v_p, out, nrows);
}

// round 15
// speedup vs baseline: 1.5354x; 1.5354x over previous
#include <cuda_runtime.h>
#include <cuda_bf16.h>
#include <math.h>
#include <stdint.h>

#define NROWS 100000
#define MTRIP 800000
#define HID   128
#define HEADS 8
#define NBLK  ((NROWS + 1023) / 1024)

// packed bf16-pair words per row: 64 + pad. 68 => (g*4+tg) distinct mod 32
#define PAD2  68
// smem: As_hi, As_lo (64 rows) + Ws_hi, Ws_lo (128 rows), uint32 words
#define GEMM_SMEM ((64 * 2 + 128 * 2) * PAD2 * 4)
#define WELEMS (HID * HID)        // 16384 per matrix
#define WPAIRS (WELEMS / 2)       // 8192 packed pairs per matrix

// ---------------- scratch (static device globals; no allocs allowed) ----------------
__device__ float    g_q[NROWS * HID];
__device__ float    g_k[NROWS * HID];
__device__ float    g_v[NROWS * HID];
__device__ float    g_agg[NROWS * HID];
__device__ uint32_t g_whi[5 * WPAIRS];   // pre-split weights (hi), 5 matrices
__device__ uint32_t g_wlo[5 * WPAIRS];   // pre-split weights (lo)
__device__ int      g_hist[NROWS + 1];
__device__ int      g_cursor[NROWS];
__device__ int      g_bsums[NBLK];
__device__ int      g_perm[MTRIP];       // stores source index kj, dest-sorted
__device__ int      g_is64;

// ---------------- index dtype detection ----------------
__global__ void detect_kernel(const unsigned int* raw, int m) {
    __shared__ int nz;
    if (threadIdx.x == 0) nz = 0;
    __syncthreads();
    int c = m < 2048 ? m : 2048;
    int local = 0;
    for (int i = threadIdx.x; i < c; i += blockDim.x)
        if (raw[2 * i + 1] != 0u) local = 1;
    if (local) atomicOr(&nz, 1);
    __syncthreads();
    if (threadIdx.x == 0) g_is64 = (nz == 0) ? 1 : 0;
}

__device__ __forceinline__ long long load_idx(const void* p, int i, bool is64) {
    return is64 ? ((const long long*)p)[i] : (long long)((const int*)p)[i];
}

// ---------------- bf16 hi/lo split helpers ----------------
__device__ __forceinline__ void split_pack(float v0, float v1,
                                           uint32_t& hi, uint32_t& lo) {
    __nv_bfloat162 h2 = __floats2bfloat162_rn(v0, v1);
    hi = *reinterpret_cast<uint32_t*>(&h2);
    float r0 = v0 - __bfloat162float(h2.x);
    float r1 = v1 - __bfloat162float(h2.y);
    __nv_bfloat162 l2 = __floats2bfloat162_rn(r0, r1);
    lo = *reinterpret_cast<uint32_t*>(&l2);
}

// ---------------- one-shot weight pre-split (5 matrices) ----------------
__global__ void prep_weights(const float* __restrict__ W0, const float* __restrict__ W1,
                             const float* __restrict__ W2, const float* __restrict__ W3,
                             const float* __restrict__ W4) {
    const float* Ws[5] = {W0, W1, W2, W3, W4};
    for (int i = blockIdx.x * blockDim.x + threadIdx.x; i < 5 * WPAIRS;
         i += gridDim.x * blockDim.x) {
        int mat = i / WPAIRS, p = i % WPAIRS;
        float2 w = ((const float2*)Ws[mat])[p];
        uint32_t h, l;
        split_pack(w.x, w.y, h, l);
        g_whi[i] = h;
        g_wlo[i] = l;
    }
}

// ---------------- counting sort by destination (idx_ji) ----------------
__global__ void zero_hist() {
    for (int i = blockIdx.x * blockDim.x + threadIdx.x; i <= NROWS;
         i += gridDim.x * blockDim.x)
        g_hist[i] = 0;
}

__global__ void hist_kernel(const void* __restrict__ idx_ji, int m) {
    bool is64 = (g_is64 != 0);
    for (int e = blockIdx.x * blockDim.x + threadIdx.x; e < m;
         e += gridDim.x * blockDim.x)
        atomicAdd(&g_hist[(int)load_idx(idx_ji, e, is64)], 1);
}

__global__ void scan1_kernel() {
    __shared__ int s[1024];
    int t = threadIdx.x;
    int i = blockIdx.x * 1024 + t;
    int v = (i < NROWS) ? g_hist[i] : 0;
    s[t] = v;
    __syncthreads();
#pragma unroll
    for (int off = 1; off < 1024; off <<= 1) {
        int x = (t >= off) ? s[t - off] : 0;
        __syncthreads();
        s[t] += x;
        __syncthreads();
    }
    if (i < NROWS) g_hist[i] = s[t] - v;   // exclusive within block
    if (t == 1023) g_bsums[blockIdx.x] = s[t];
}

__global__ void scan2_kernel() {
    int running = 0;
    for (int b = 0; b < NBLK; ++b) {
        int t = g_bsums[b];
        g_bsums[b] = running;
        running += t;
    }
    g_hist[NROWS] = running;   // = M
}

__global__ void scan3_kernel() {
    for (int i = blockIdx.x * blockDim.x + threadIdx.x; i < NROWS;
         i += gridDim.x * blockDim.x) {
        int v = g_hist[i] + g_bsums[i >> 10];
        g_hist[i] = v;
        g_cursor[i] = v;
    }
}

__global__ void scatter_kernel(const void* __restrict__ idx_ji,
                               const void* __restrict__ idx_kj, int m) {
    bool is64 = (g_is64 != 0);
    for (int e = blockIdx.x * blockDim.x + threadIdx.x; e < m;
         e += gridDim.x * blockDim.x) {
        int d = (int)load_idx(idx_ji, e, is64);
        int src = (int)load_idx(idx_kj, e, is64);
        int pos = atomicAdd(&g_cursor[d], 1);
        g_perm[pos] = src;
    }
}

// ================== bf16x2 3-term GEMM via mma.sync.m16n8k16 =======================
__device__ __forceinline__ void mma16(float c[4], const uint32_t a[4],
                                      const uint32_t b[2]) {
    asm volatile(
        "mma.sync.aligned.m16n8k16.row.col.f32.bf16.bf16.f32 "
        "{%0,%1,%2,%3}, {%4,%5,%6,%7}, {%8,%9}, {%0,%1,%2,%3};"
        : "+f"(c[0]), "+f"(c[1]), "+f"(c[2]), "+f"(c[3])
        : "r"(a[0]), "r"(a[1]), "r"(a[2]), "r"(a[3]), "r"(b[0]), "r"(b[1]));
}

// Core: copies pre-split W into SMEM, runs 8 k16-steps of bf16x2 3-term MMA.
// widx selects the matrix in g_whi/g_wlo.
// mode 0: write out rows (optional bias/relu/addsrc)
// mode 1: write relu(x + bias) back into As_hi/As_lo (for fused MLP middle layer)
__device__ __noinline__ void gemm_core(uint32_t* As_hi, uint32_t* As_lo,
                                       uint32_t* Ws_hi, uint32_t* Ws_lo,
                                       int widx,
                                       const float* __restrict__ bias,
                                       const float* __restrict__ addsrc,
                                       float* __restrict__ out,
                                       int nrows, int row0, int dorelu, int mode) {
    const int tid = threadIdx.x;
    const int lane = tid & 31;
    const int wid = tid >> 5;
    const int wm = wid & 1, wn = wid >> 1;   // warp tile 32x32
    const int g = lane >> 2, tg = lane & 3;
    const uint32_t* Whi = g_whi + widx * WPAIRS;
    const uint32_t* Wlo = g_wlo + widx * WPAIRS;

    __syncthreads();   // previous consumers of Ws / As writers done
    // stage W: pure word copies of pre-split pairs (8192 words each)
#pragma unroll
    for (int it = 0; it < 16; ++it) {
        int e2 = tid + it * 256;          // uint2 index: 4096 total
        int e = e2 * 2;
        int o = e >> 6, p = e & 63;
        uint2 h = ((const uint2*)Whi)[e2];
        uint2 l = ((const uint2*)Wlo)[e2];
        Ws_hi[o * PAD2 + p] = h.x;
        Ws_hi[o * PAD2 + p + 1] = h.y;
        Ws_lo[o * PAD2 + p] = l.x;
        Ws_lo[o * PAD2 + p + 1] = l.y;
    }
    __syncthreads();

    float acc[2][4][4];
#pragma unroll
    for (int i = 0; i < 2; ++i)
#pragma unroll
        for (int j = 0; j < 4; ++j)
#pragma unroll
            for (int q = 0; q < 4; ++q) acc[i][j][q] = 0.f;

#pragma unroll
    for (int ks = 0; ks < 8; ++ks) {
        const int kp = ks * 8;
        uint32_t ah[2][4], al[2][4], bh[4][2], bl[4][2];
#pragma unroll
        for (int mf = 0; mf < 2; ++mf) {
            int br = wm * 32 + mf * 16;
            ah[mf][0] = As_hi[(br + g) * PAD2 + kp + tg];
            ah[mf][1] = As_hi[(br + g + 8) * PAD2 + kp + tg];
            ah[mf][2] = As_hi[(br + g) * PAD2 + kp + tg + 4];
            ah[mf][3] = As_hi[(br + g + 8) * PAD2 + kp + tg + 4];
            al[mf][0] = As_lo[(br + g) * PAD2 + kp + tg];
            al[mf][1] = As_lo[(br + g + 8) * PAD2 + kp + tg];
            al[mf][2] = As_lo[(br + g) * PAD2 + kp + tg + 4];
            al[mf][3] = As_lo[(br + g + 8) * PAD2 + kp + tg + 4];
        }
#pragma unroll
        for (int nf = 0; nf < 4; ++nf) {
            int col = wn * 32 + nf * 8 + g;
            bh[nf][0] = Ws_hi[col * PAD2 + kp + tg];
            bh[nf][1] = Ws_hi[col * PAD2 + kp + tg + 4];
            bl[nf][0] = Ws_lo[col * PAD2 + kp + tg];
            bl[nf][1] = Ws_lo[col * PAD2 + kp + tg + 4];
        }
#pragma unroll
        for (int mf = 0; mf < 2; ++mf)
#pragma unroll
            for (int nf = 0; nf < 4; ++nf) {
                mma16(acc[mf][nf], ah[mf], bh[nf]);
                mma16(acc[mf][nf], ah[mf], bl[nf]);
                mma16(acc[mf][nf], al[mf], bh[nf]);
            }
    }

    if (mode == 1) {
        // fused-MLP middle layer: h = relu(x + bias) -> back into As (split bf16)
        __syncthreads();   // all warps done reading As
#pragma unroll
        for (int mf = 0; mf < 2; ++mf) {
#pragma unroll
            for (int half = 0; half < 2; ++half) {
                int rl = wm * 32 + mf * 16 + g + half * 8;
#pragma unroll
                for (int nf = 0; nf < 4; ++nf) {
                    int col = wn * 32 + nf * 8 + 2 * tg;
                    float x = fmaxf(acc[mf][nf][half * 2 + 0] + bias[col], 0.f);
                    float y = fmaxf(acc[mf][nf][half * 2 + 1] + bias[col + 1], 0.f);
                    uint32_t h, l;
                    split_pack(x, y, h, l);
                    int wx = rl * PAD2 + wn * 16 + nf * 4 + tg;
                    As_hi[wx] = h;
                    As_lo[wx] = l;
                }
            }
        }
        return;   // caller's next gemm_core starts with __syncthreads()
    }

    // epilogue to gmem
#pragma unroll
    for (int mf = 0; mf < 2; ++mf) {
#pragma unroll
        for (int half = 0; half < 2; ++half) {
            int r = row0 + wm * 32 + mf * 16 + g + half * 8;
            if (r >= nrows) continue;
#pragma unroll
            for (int nf = 0; nf < 4; ++nf) {
                int col = wn * 32 + nf * 8 + 2 * tg;
                float x = acc[mf][nf][half * 2 + 0];
                float y = acc[mf][nf][half * 2 + 1];
                if (bias) { x += bias[col]; y += bias[col + 1]; }
                if (dorelu) { x = fmaxf(x, 0.f); y = fmaxf(y, 0.f); }
                if (addsrc) {
                    const float* ap = addsrc + (size_t)r * HID + col;
                    x += ap[0]; y += ap[1];
                }
                *(float2*)(out + (size_t)r * HID + col) = make_float2(x, y);
            }
        }
    }
}

// ---- stage 64-row fp32 A tile into SMEM as split bf16 pairs ----
__device__ __forceinline__ void stage_A(uint32_t* As_hi, uint32_t* As_lo,
                                        const float* __restrict__ A,
                                        int nrows, int row0) {
    const int tid = threadIdx.x;
#pragma unroll
    for (int it = 0; it < 16; ++it) {
        int e = tid + it * 256;       // 64 rows x 64 pairs = 4096 words
        int r = e >> 6, p = e & 63;
        float2 a = make_float2(0.f, 0.f);
        if (row0 + r < nrows)
            a = ((const float2*)(A + (size_t)(row0 + r) * HID))[p];
        uint32_t h, l;
        split_pack(a.x, a.y, h, l);
        As_hi[r * PAD2 + p] = h;
        As_lo[r * PAD2 + p] = l;
    }
}

// ---- fused Q/K/V projection (weights 0=Wq, 1=Wk, 2=Wv pre-split) ----
__global__ __launch_bounds__(256, 2)
void gemm_qkv(const float* __restrict__ feats,
              float* __restrict__ q, float* __restrict__ k, float* __restrict__ v,
              int nrows) {
    extern __shared__ uint32_t smem_u[];
    uint32_t* As_hi = smem_u;
    uint32_t* As_lo = As_hi + 64 * PAD2;
    uint32_t* Ws_hi = As_lo + 64 * PAD2;
    uint32_t* Ws_lo = Ws_hi + 128 * PAD2;
    int row0 = blockIdx.x * 64;
    stage_A(As_hi, As_lo, feats, nrows, row0);
    gemm_core(As_hi, As_lo, Ws_hi, Ws_lo, 0, nullptr, nullptr, q, nrows, row0, 0, 0);
    gemm_core(As_hi, As_lo, Ws_hi, Ws_lo, 1, nullptr, nullptr, k, nrows, row0, 0, 0);
    gemm_core(As_hi, As_lo, Ws_hi, Ws_lo, 2, nullptr, nullptr, v, nrows, row0, 0, 0);
}

// ---- fused MLP: out = v + relu(W2 @ relu(W1 @ agg + b1) + b2); weights 3,4 ----
__global__ __launch_bounds__(256, 2)
void gemm_mlp(const float* __restrict__ b1, const float* __restrict__ b2,
              const float* __restrict__ v, float* __restrict__ out, int nrows) {
    extern __shared__ uint32_t smem_u[];
    uint32_t* As_hi = smem_u;
    uint32_t* As_lo = As_hi + 64 * PAD2;
    uint32_t* Ws_hi = As_lo + 64 * PAD2;
    uint32_t* Ws_lo = Ws_hi + 128 * PAD2;
    int row0 = blockIdx.x * 64;
    stage_A(As_hi, As_lo, g_agg, nrows, row0);
    gemm_core(As_hi, As_lo, Ws_hi, Ws_lo, 3, b1, nullptr, nullptr, nrows, row0, 1, 1);
    gemm_core(As_hi, As_lo, Ws_hi, Ws_lo, 4, b2, v, out, nrows, row0, 1, 0);
}

// ---- edge attention accumulate for one edge source ----
__device__ __forceinline__ void att_edge(int kj, int lane, const float4& kv,
                                         float4& acc, float& denom) {
    float4 qv = ((const float4*)g_q)[(size_t)kj * 32 + lane];
    float4 vv = ((const float4*)g_v)[(size_t)kj * 32 + lane];
    float d = qv.x * kv.x + qv.y * kv.y + qv.z * kv.z + qv.w * kv.w;
    d += __shfl_xor_sync(0xffffffffu, d, 1);
    d += __shfl_xor_sync(0xffffffffu, d, 2);
    float s = d > 0.f ? d : 0.2f * d;     // leaky_relu(0.2)
    float a = expf(s);
    denom += a;
    acc.x += a * vv.x; acc.y += a * vv.y;
    acc.z += a * vv.z; acc.w += a * vv.w;
}

// ---- fused attention + aggregation, warp per destination node (R7 structure) ------
__global__ void att_agg_kernel() {
    int n = (blockIdx.x * blockDim.x + threadIdx.x) >> 5;
    if (n >= NROWS) return;
    int lane = threadIdx.x & 31;

    int start = g_hist[n], end = g_hist[n + 1];
    float4 kv = ((const float4*)g_k)[(size_t)n * 32 + lane];
    float4 acc = make_float4(0.f, 0.f, 0.f, 0.f);
    float denom = 0.f;

    int p = start;
    for (; p + 2 <= end; p += 2) {
        int kj0 = __ldg(&g_perm[p]);
        int kj1 = __ldg(&g_perm[p + 1]);
        float4 q0 = ((const float4*)g_q)[(size_t)kj0 * 32 + lane];
        float4 v0 = ((const float4*)g_v)[(size_t)kj0 * 32 + lane];
        float4 q1 = ((const float4*)g_q)[(size_t)kj1 * 32 + lane];
        float4 v1 = ((const float4*)g_v)[(size_t)kj1 * 32 + lane];
        float d0 = q0.x * kv.x + q0.y * kv.y + q0.z * kv.z + q0.w * kv.w;
        float d1 = q1.x * kv.x + q1.y * kv.y + q1.z * kv.z + q1.w * kv.w;
        d0 += __shfl_xor_sync(0xffffffffu, d0, 1);
        d1 += __shfl_xor_sync(0xffffffffu, d1, 1);
        d0 += __shfl_xor_sync(0xffffffffu, d0, 2);
        d1 += __shfl_xor_sync(0xffffffffu, d1, 2);
        float s0 = d0 > 0.f ? d0 : 0.2f * d0;
        float s1 = d1 > 0.f ? d1 : 0.2f * d1;
        float a0 = expf(s0);
        float a1 = expf(s1);
        denom += a0 + a1;
        acc.x += a0 * v0.x + a1 * v1.x;
        acc.y += a0 * v0.y + a1 * v1.y;
        acc.z += a0 * v0.z + a1 * v1.z;
        acc.w += a0 * v0.w + a1 * v1.w;
    }
    if (p < end) {
        att_edge(__ldg(&g_perm[p]), lane, kv, acc, denom);
    }

    float inv = (end > start) ? 1.f / denom : 0.f;
    float4 o = make_float4(acc.x * inv, acc.y * inv, acc.z * inv, acc.w * inv);
    ((float4*)g_agg)[(size_t)n * 32 + lane] = o;
}

// ---------------- launch ----------------
extern "C" void kernel_launch(void* const* d_in, const int* in_sizes, int n_in,
                              void* d_out, int out_size) {
    const float* feats = (const float*)d_in[0];
    const void*  idx_kj = d_in[1];
    const void*  idx_ji = d_in[2];
    const float* Wv = (const float*)d_in[3];
    const float* Wq = (const float*)d_in[4];
    const float* Wk = (const float*)d_in[5];
    const float* W1 = (const float*)d_in[6];
    const float* b1 = (const float*)d_in[7];
    const float* W2 = (const float*)d_in[8];
    const float* b2 = (const float*)d_in[9];
    float* out = (float*)d_out;

    int nrows = in_sizes[0] / HID;
    int m     = in_sizes[1];

    float *q_p, *k_p, *v_p;
    cudaGetSymbolAddress((void**)&q_p, g_q);
    cudaGetSymbolAddress((void**)&k_p, g_k);
    cudaGetSymbolAddress((void**)&v_p, g_v);

    cudaFuncSetAttribute(gemm_qkv, cudaFuncAttributeMaxDynamicSharedMemorySize,
                         GEMM_SMEM);
    cudaFuncSetAttribute(gemm_mlp, cudaFuncAttributeMaxDynamicSharedMemorySize,
                         GEMM_SMEM);

    // side stream + events (created once; reused across graph captures)
    static cudaStream_t s_side = nullptr;
    static cudaEvent_t  ev_fork = nullptr, ev_join = nullptr, ev_prep = nullptr;
    if (!s_side) {
        cudaStreamCreateWithFlags(&s_side, cudaStreamNonBlocking);
        cudaEventCreateWithFlags(&ev_fork, cudaEventDisableTiming);
        cudaEventCreateWithFlags(&ev_join, cudaEventDisableTiming);
        cudaEventCreateWithFlags(&ev_prep, cudaEventDisableTiming);
    }

    // fork: weight pre-split + sort on the side stream (overlaps gemm_qkv tail)
    cudaEventRecord(ev_fork, 0);
    cudaStreamWaitEvent(s_side, ev_fork, 0);
    prep_weights<<<160, 256, 0, s_side>>>(Wq, Wk, Wv, W1, W2);
    cudaEventRecord(ev_prep, s_side);          // gemm_qkv needs split weights
    detect_kernel<<<1, 256, 0, s_side>>>((const unsigned int*)idx_kj, m);
    zero_hist<<<256, 256, 0, s_side>>>();
    hist_kernel<<<1024, 256, 0, s_side>>>(idx_ji, m);
    scan1_kernel<<<NBLK, 1024, 0, s_side>>>();
    scan2_kernel<<<1, 1, 0, s_side>>>();
    scan3_kernel<<<256, 256, 0, s_side>>>();
    scatter_kernel<<<1024, 256, 0, s_side>>>(idx_ji, idx_kj, m);
    cudaEventRecord(ev_join, s_side);

    // main stream: QKV projections (wait only for the weight pre-split)
    cudaStreamWaitEvent(0, ev_prep, 0);
    int gblocks = (nrows + 63) / 64;
    gemm_qkv<<<gblocks, 256, GEMM_SMEM>>>(feats, q_p, k_p, v_p, nrows);

    // join sort, then attention + fused MLP
    cudaStreamWaitEvent(0, ev_join, 0);
    int ablocks = (NROWS * 32 + 255) / 256;
    att_agg_kernel<<<ablocks, 256>>>();

    gemm_mlp<<<gblocks, 256, GEMM_SMEM>>>(b1, b2, v_p, out, nrows);
}

// round 16
// speedup vs baseline: 1.5357x; 1.0002x over previous
#include <cuda_runtime.h>
#include <cuda_bf16.h>
#include <math.h>
#include <stdint.h>

#define NROWS 100000
#define MTRIP 800000
#define HID   128
#define HEADS 8
#define NBLK  ((NROWS + 1023) / 1024)

// packed bf16-pair words per row: 64 + pad. 68 => (g*4+tg) distinct mod 32
#define PAD2  68
// smem: As_hi, As_lo (64 rows) + Ws_hi, Ws_lo (128 rows), uint32 words
#define GEMM_SMEM ((64 * 2 + 128 * 2) * PAD2 * 4)
#define WELEMS (HID * HID)        // 16384 per matrix
#define WPAIRS (WELEMS / 2)       // 8192 packed pairs per matrix

// ---------------- scratch (static device globals; no allocs allowed) ----------------
__device__ float    g_q[NROWS * HID];
__device__ float    g_k[NROWS * HID];
__device__ float    g_v[NROWS * HID];
__device__ uint32_t g_agg_hi[NROWS * 64];  // agg pre-split bf16 pairs (hi)
__device__ uint32_t g_agg_lo[NROWS * 64];  // agg pre-split bf16 pairs (lo)
__device__ uint32_t g_whi[5 * WPAIRS];     // pre-split weights (hi), 5 matrices
__device__ uint32_t g_wlo[5 * WPAIRS];     // pre-split weights (lo)
__device__ int      g_hist[NROWS + 1];
__device__ int      g_cursor[NROWS];
__device__ int      g_bsums[NBLK];
__device__ int      g_perm[MTRIP];         // stores source index kj, dest-sorted
__device__ int      g_is64;

// ---------------- index dtype detection ----------------
__global__ void detect_kernel(const unsigned int* raw, int m) {
    __shared__ int nz;
    if (threadIdx.x == 0) nz = 0;
    __syncthreads();
    int c = m < 2048 ? m : 2048;
    int local = 0;
    for (int i = threadIdx.x; i < c; i += blockDim.x)
        if (raw[2 * i + 1] != 0u) local = 1;
    if (local) atomicOr(&nz, 1);
    __syncthreads();
    if (threadIdx.x == 0) g_is64 = (nz == 0) ? 1 : 0;
}

__device__ __forceinline__ long long load_idx(const void* p, int i, bool is64) {
    return is64 ? ((const long long*)p)[i] : (long long)((const int*)p)[i];
}

// ---------------- bf16 hi/lo split helpers ----------------
__device__ __forceinline__ void split_pack(float v0, float v1,
                                           uint32_t& hi, uint32_t& lo) {
    __nv_bfloat162 h2 = __floats2bfloat162_rn(v0, v1);
    hi = *reinterpret_cast<uint32_t*>(&h2);
    float r0 = v0 - __bfloat162float(h2.x);
    float r1 = v1 - __bfloat162float(h2.y);
    __nv_bfloat162 l2 = __floats2bfloat162_rn(r0, r1);
    lo = *reinterpret_cast<uint32_t*>(&l2);
}

// ---------------- one-shot weight pre-split (5 matrices) ----------------
__global__ void prep_weights(const float* __restrict__ W0, const float* __restrict__ W1,
                             const float* __restrict__ W2, const float* __restrict__ W3,
                             const float* __restrict__ W4) {
    const float* Ws[5] = {W0, W1, W2, W3, W4};
    for (int i = blockIdx.x * blockDim.x + threadIdx.x; i < 5 * WPAIRS;
         i += gridDim.x * blockDim.x) {
        int mat = i / WPAIRS, p = i % WPAIRS;
        float2 w = ((const float2*)Ws[mat])[p];
        uint32_t h, l;
        split_pack(w.x, w.y, h, l);
        g_whi[i] = h;
        g_wlo[i] = l;
    }
}

// ---------------- counting sort by destination (idx_ji) ----------------
__global__ void zero_hist() {
    for (int i = blockIdx.x * blockDim.x + threadIdx.x; i <= NROWS;
         i += gridDim.x * blockDim.x)
        g_hist[i] = 0;
}

__global__ void hist_kernel(const void* __restrict__ idx_ji, int m) {
    bool is64 = (g_is64 != 0);
    for (int e = blockIdx.x * blockDim.x + threadIdx.x; e < m;
         e += gridDim.x * blockDim.x)
        atomicAdd(&g_hist[(int)load_idx(idx_ji, e, is64)], 1);
}

__global__ void scan1_kernel() {
    __shared__ int s[1024];
    int t = threadIdx.x;
    int i = blockIdx.x * 1024 + t;
    int v = (i < NROWS) ? g_hist[i] : 0;
    s[t] = v;
    __syncthreads();
#pragma unroll
    for (int off = 1; off < 1024; off <<= 1) {
        int x = (t >= off) ? s[t - off] : 0;
        __syncthreads();
        s[t] += x;
        __syncthreads();
    }
    if (i < NROWS) g_hist[i] = s[t] - v;   // exclusive within block
    if (t == 1023) g_bsums[blockIdx.x] = s[t];
}

__global__ void scan2_kernel() {
    int running = 0;
    for (int b = 0; b < NBLK; ++b) {
        int t = g_bsums[b];
        g_bsums[b] = running;
        running += t;
    }
    g_hist[NROWS] = running;   // = M
}

__global__ void scan3_kernel() {
    for (int i = blockIdx.x * blockDim.x + threadIdx.x; i < NROWS;
         i += gridDim.x * blockDim.x) {
        int v = g_hist[i] + g_bsums[i >> 10];
        g_hist[i] = v;
        g_cursor[i] = v;
    }
}

__global__ void scatter_kernel(const void* __restrict__ idx_ji,
                               const void* __restrict__ idx_kj, int m) {
    bool is64 = (g_is64 != 0);
    for (int e = blockIdx.x * blockDim.x + threadIdx.x; e < m;
         e += gridDim.x * blockDim.x) {
        int d = (int)load_idx(idx_ji, e, is64);
        int src = (int)load_idx(idx_kj, e, is64);
        int pos = atomicAdd(&g_cursor[d], 1);
        g_perm[pos] = src;
    }
}

// ================== bf16x2 3-term GEMM via mma.sync.m16n8k16 =======================
__device__ __forceinline__ void mma16(float c[4], const uint32_t a[4],
                                      const uint32_t b[2]) {
    asm volatile(
        "mma.sync.aligned.m16n8k16.row.col.f32.bf16.bf16.f32 "
        "{%0,%1,%2,%3}, {%4,%5,%6,%7}, {%8,%9}, {%0,%1,%2,%3};"
        : "+f"(c[0]), "+f"(c[1]), "+f"(c[2]), "+f"(c[3])
        : "r"(a[0]), "r"(a[1]), "r"(a[2]), "r"(a[3]), "r"(b[0]), "r"(b[1]));
}

// Core: copies pre-split W into SMEM, runs 8 k16-steps of bf16x2 3-term MMA.
// widx selects the matrix in g_whi/g_wlo.
// mode 0: write out rows (optional bias/relu/addsrc)
// mode 1: write relu(x + bias) back into As_hi/As_lo (for fused MLP middle layer)
__device__ __noinline__ void gemm_core(uint32_t* As_hi, uint32_t* As_lo,
                                       uint32_t* Ws_hi, uint32_t* Ws_lo,
                                       int widx,
                                       const float* __restrict__ bias,
                                       const float* __restrict__ addsrc,
                                       float* __restrict__ out,
                                       int nrows, int row0, int dorelu, int mode) {
    const int tid = threadIdx.x;
    const int lane = tid & 31;
    const int wid = tid >> 5;
    const int wm = wid & 1, wn = wid >> 1;   // warp tile 32x32
    const int g = lane >> 2, tg = lane & 3;
    const uint32_t* Whi = g_whi + widx * WPAIRS;
    const uint32_t* Wlo = g_wlo + widx * WPAIRS;

    __syncthreads();   // previous consumers of Ws / As writers done
    // stage W: pure word copies of pre-split pairs (8192 words each)
#pragma unroll
    for (int it = 0; it < 16; ++it) {
        int e2 = tid + it * 256;          // uint2 index: 4096 total
        int e = e2 * 2;
        int o = e >> 6, p = e & 63;
        uint2 h = ((const uint2*)Whi)[e2];
        uint2 l = ((const uint2*)Wlo)[e2];
        Ws_hi[o * PAD2 + p] = h.x;
        Ws_hi[o * PAD2 + p + 1] = h.y;
        Ws_lo[o * PAD2 + p] = l.x;
        Ws_lo[o * PAD2 + p + 1] = l.y;
    }
    __syncthreads();

    float acc[2][4][4];
#pragma unroll
    for (int i = 0; i < 2; ++i)
#pragma unroll
        for (int j = 0; j < 4; ++j)
#pragma unroll
            for (int q = 0; q < 4; ++q) acc[i][j][q] = 0.f;

#pragma unroll
    for (int ks = 0; ks < 8; ++ks) {
        const int kp = ks * 8;
        uint32_t ah[2][4], al[2][4], bh[4][2], bl[4][2];
#pragma unroll
        for (int mf = 0; mf < 2; ++mf) {
            int br = wm * 32 + mf * 16;
            ah[mf][0] = As_hi[(br + g) * PAD2 + kp + tg];
            ah[mf][1] = As_hi[(br + g + 8) * PAD2 + kp + tg];
            ah[mf][2] = As_hi[(br + g) * PAD2 + kp + tg + 4];
            ah[mf][3] = As_hi[(br + g + 8) * PAD2 + kp + tg + 4];
            al[mf][0] = As_lo[(br + g) * PAD2 + kp + tg];
            al[mf][1] = As_lo[(br + g + 8) * PAD2 + kp + tg];
            al[mf][2] = As_lo[(br + g) * PAD2 + kp + tg + 4];
            al[mf][3] = As_lo[(br + g + 8) * PAD2 + kp + tg + 4];
        }
#pragma unroll
        for (int nf = 0; nf < 4; ++nf) {
            int col = wn * 32 + nf * 8 + g;
            bh[nf][0] = Ws_hi[col * PAD2 + kp + tg];
            bh[nf][1] = Ws_hi[col * PAD2 + kp + tg + 4];
            bl[nf][0] = Ws_lo[col * PAD2 + kp + tg];
            bl[nf][1] = Ws_lo[col * PAD2 + kp + tg + 4];
        }
#pragma unroll
        for (int mf = 0; mf < 2; ++mf)
#pragma unroll
            for (int nf = 0; nf < 4; ++nf) {
                mma16(acc[mf][nf], ah[mf], bh[nf]);
                mma16(acc[mf][nf], ah[mf], bl[nf]);
                mma16(acc[mf][nf], al[mf], bh[nf]);
            }
    }

    if (mode == 1) {
        // fused-MLP middle layer: h = relu(x + bias) -> back into As (split bf16)
        __syncthreads();   // all warps done reading As
#pragma unroll
        for (int mf = 0; mf < 2; ++mf) {
#pragma unroll
            for (int half = 0; half < 2; ++half) {
                int rl = wm * 32 + mf * 16 + g + half * 8;
#pragma unroll
                for (int nf = 0; nf < 4; ++nf) {
                    int col = wn * 32 + nf * 8 + 2 * tg;
                    float x = fmaxf(acc[mf][nf][half * 2 + 0] + bias[col], 0.f);
                    float y = fmaxf(acc[mf][nf][half * 2 + 1] + bias[col + 1], 0.f);
                    uint32_t h, l;
                    split_pack(x, y, h, l);
                    int wx = rl * PAD2 + wn * 16 + nf * 4 + tg;
                    As_hi[wx] = h;
                    As_lo[wx] = l;
                }
            }
        }
        return;   // caller's next gemm_core starts with __syncthreads()
    }

    // epilogue to gmem
#pragma unroll
    for (int mf = 0; mf < 2; ++mf) {
#pragma unroll
        for (int half = 0; half < 2; ++half) {
            int r = row0 + wm * 32 + mf * 16 + g + half * 8;
            if (r >= nrows) continue;
#pragma unroll
            for (int nf = 0; nf < 4; ++nf) {
                int col = wn * 32 + nf * 8 + 2 * tg;
                float x = acc[mf][nf][half * 2 + 0];
                float y = acc[mf][nf][half * 2 + 1];
                if (bias) { x += bias[col]; y += bias[col + 1]; }
                if (dorelu) { x = fmaxf(x, 0.f); y = fmaxf(y, 0.f); }
                if (addsrc) {
                    const float* ap = addsrc + (size_t)r * HID + col;
                    x += ap[0]; y += ap[1];
                }
                *(float2*)(out + (size_t)r * HID + col) = make_float2(x, y);
            }
        }
    }
}

// ---- stage 64-row fp32 A tile into SMEM as split bf16 pairs ----
__device__ __forceinline__ void stage_A(uint32_t* As_hi, uint32_t* As_lo,
                                        const float* __restrict__ A,
                                        int nrows, int row0) {
    const int tid = threadIdx.x;
#pragma unroll
    for (int it = 0; it < 16; ++it) {
        int e = tid + it * 256;       // 64 rows x 64 pairs = 4096 words
        int r = e >> 6, p = e & 63;
        float2 a = make_float2(0.f, 0.f);
        if (row0 + r < nrows)
            a = ((const float2*)(A + (size_t)(row0 + r) * HID))[p];
        uint32_t h, l;
        split_pack(a.x, a.y, h, l);
        As_hi[r * PAD2 + p] = h;
        As_lo[r * PAD2 + p] = l;
    }
}

// ---- stage 64-row pre-split agg tile (pure word copies, no cvt) ----
__device__ __forceinline__ void stage_A_presplit(uint32_t* As_hi, uint32_t* As_lo,
                                                 int nrows, int row0) {
    const int tid = threadIdx.x;
#pragma unroll
    for (int it = 0; it < 8; ++it) {
        int e2 = tid + it * 256;          // uint2 index: 2048 total
        int e = e2 * 2;
        int r = e >> 6, p = e & 63;
        uint2 h = make_uint2(0u, 0u), l = make_uint2(0u, 0u);
        if (row0 + r < nrows) {
            h = ((const uint2*)g_agg_hi)[(size_t)(row0 + r) * 32 + (p >> 1)];
            l = ((const uint2*)g_agg_lo)[(size_t)(row0 + r) * 32 + (p >> 1)];
        }
        As_hi[r * PAD2 + p] = h.x;
        As_hi[r * PAD2 + p + 1] = h.y;
        As_lo[r * PAD2 + p] = l.x;
        As_lo[r * PAD2 + p + 1] = l.y;
    }
}

// ---- fused Q/K/V projection (weights 0=Wq, 1=Wk, 2=Wv pre-split) ----
__global__ __launch_bounds__(256, 2)
void gemm_qkv(const float* __restrict__ feats,
              float* __restrict__ q, float* __restrict__ k, float* __restrict__ v,
              int nrows) {
    extern __shared__ uint32_t smem_u[];
    uint32_t* As_hi = smem_u;
    uint32_t* As_lo = As_hi + 64 * PAD2;
    uint32_t* Ws_hi = As_lo + 64 * PAD2;
    uint32_t* Ws_lo = Ws_hi + 128 * PAD2;
    int row0 = blockIdx.x * 64;
    stage_A(As_hi, As_lo, feats, nrows, row0);
    gemm_core(As_hi, As_lo, Ws_hi, Ws_lo, 0, nullptr, nullptr, q, nrows, row0, 0, 0);
    gemm_core(As_hi, As_lo, Ws_hi, Ws_lo, 1, nullptr, nullptr, k, nrows, row0, 0, 0);
    gemm_core(As_hi, As_lo, Ws_hi, Ws_lo, 2, nullptr, nullptr, v, nrows, row0, 0, 0);
}

// ---- fused MLP: out = v + relu(W2 @ relu(W1 @ agg + b1) + b2); weights 3,4 ----
__global__ __launch_bounds__(256, 2)
void gemm_mlp(const float* __restrict__ b1, const float* __restrict__ b2,
              const float* __restrict__ v, float* __restrict__ out, int nrows) {
    extern __shared__ uint32_t smem_u[];
    uint32_t* As_hi = smem_u;
    uint32_t* As_lo = As_hi + 64 * PAD2;
    uint32_t* Ws_hi = As_lo + 64 * PAD2;
    uint32_t* Ws_lo = Ws_hi + 128 * PAD2;
    int row0 = blockIdx.x * 64;
    stage_A_presplit(As_hi, As_lo, nrows, row0);
    gemm_core(As_hi, As_lo, Ws_hi, Ws_lo, 3, b1, nullptr, nullptr, nrows, row0, 1, 1);
    gemm_core(As_hi, As_lo, Ws_hi, Ws_lo, 4, b2, v, out, nrows, row0, 1, 0);
}

// ---- edge attention accumulate for one edge source ----
__device__ __forceinline__ void att_edge(int kj, int lane, const float4& kv,
                                         float4& acc, float& denom) {
    float4 qv = ((const float4*)g_q)[(size_t)kj * 32 + lane];
    float4 vv = ((const float4*)g_v)[(size_t)kj * 32 + lane];
    float d = qv.x * kv.x + qv.y * kv.y + qv.z * kv.z + qv.w * kv.w;
    d += __shfl_xor_sync(0xffffffffu, d, 1);
    d += __shfl_xor_sync(0xffffffffu, d, 2);
    float s = d > 0.f ? d : 0.2f * d;     // leaky_relu(0.2)
    float a = expf(s);
    denom += a;
    acc.x += a * vv.x; acc.y += a * vv.y;
    acc.z += a * vv.z; acc.w += a * vv.w;
}

// ---- fused attention + aggregation, warp per destination node (R7 structure) ------
__global__ void att_agg_kernel() {
    int n = (blockIdx.x * blockDim.x + threadIdx.x) >> 5;
    if (n >= NROWS) return;
    int lane = threadIdx.x & 31;

    int start = g_hist[n], end = g_hist[n + 1];
    float4 kv = ((const float4*)g_k)[(size_t)n * 32 + lane];
    float4 acc = make_float4(0.f, 0.f, 0.f, 0.f);
    float denom = 0.f;

    int p = start;
    for (; p + 2 <= end; p += 2) {
        int kj0 = __ldg(&g_perm[p]);
        int kj1 = __ldg(&g_perm[p + 1]);
        float4 q0 = ((const float4*)g_q)[(size_t)kj0 * 32 + lane];
        float4 v0 = ((const float4*)g_v)[(size_t)kj0 * 32 + lane];
        float4 q1 = ((const float4*)g_q)[(size_t)kj1 * 32 + lane];
        float4 v1 = ((const float4*)g_v)[(size_t)kj1 * 32 + lane];
        float d0 = q0.x * kv.x + q0.y * kv.y + q0.z * kv.z + q0.w * kv.w;
        float d1 = q1.x * kv.x + q1.y * kv.y + q1.z * kv.z + q1.w * kv.w;
        d0 += __shfl_xor_sync(0xffffffffu, d0, 1);
        d1 += __shfl_xor_sync(0xffffffffu, d1, 1);
        d0 += __shfl_xor_sync(0xffffffffu, d0, 2);
        d1 += __shfl_xor_sync(0xffffffffu, d1, 2);
        float s0 = d0 > 0.f ? d0 : 0.2f * d0;
        float s1 = d1 > 0.f ? d1 : 0.2f * d1;
        float a0 = expf(s0);
        float a1 = expf(s1);
        denom += a0 + a1;
        acc.x += a0 * v0.x + a1 * v1.x;
        acc.y += a0 * v0.y + a1 * v1.y;
        acc.z += a0 * v0.z + a1 * v1.z;
        acc.w += a0 * v0.w + a1 * v1.w;
    }
    if (p < end) {
        att_edge(__ldg(&g_perm[p]), lane, kv, acc, denom);
    }

    float inv = (end > start) ? 1.f / denom : 0.f;
    acc.x *= inv; acc.y *= inv; acc.z *= inv; acc.w *= inv;

    // write agg pre-split as packed bf16 pairs (same split, same values as
    // the old gemm_mlp stage_A — numerics identical)
    uint32_t h0, l0, h1, l1;
    split_pack(acc.x, acc.y, h0, l0);
    split_pack(acc.z, acc.w, h1, l1);
    ((uint2*)g_agg_hi)[(size_t)n * 32 + lane] = make_uint2(h0, h1);
    ((uint2*)g_agg_lo)[(size_t)n * 32 + lane] = make_uint2(l0, l1);
}

// ---------------- launch ----------------
extern "C" void kernel_launch(void* const* d_in, const int* in_sizes, int n_in,
                              void* d_out, int out_size) {
    const float* feats = (const float*)d_in[0];
    const void*  idx_kj = d_in[1];
    const void*  idx_ji = d_in[2];
    const float* Wv = (const float*)d_in[3];
    const float* Wq = (const float*)d_in[4];
    const float* Wk = (const float*)d_in[5];
    const float* W1 = (const float*)d_in[6];
    const float* b1 = (const float*)d_in[7];
    const float* W2 = (const float*)d_in[8];
    const float* b2 = (const float*)d_in[9];
    float* out = (float*)d_out;

    int nrows = in_sizes[0] / HID;
    int m     = in_sizes[1];

    float *q_p, *k_p, *v_p;
    cudaGetSymbolAddress((void**)&q_p, g_q);
    cudaGetSymbolAddress((void**)&k_p, g_k);
    cudaGetSymbolAddress((void**)&v_p, g_v);

    cudaFuncSetAttribute(gemm_qkv, cudaFuncAttributeMaxDynamicSharedMemorySize,
                         GEMM_SMEM);
    cudaFuncSetAttribute(gemm_mlp, cudaFuncAttributeMaxDynamicSharedMemorySize,
                         GEMM_SMEM);

    // side stream + events (created once; reused across graph captures)
    static cudaStream_t s_side = nullptr;
    static cudaEvent_t  ev_fork = nullptr, ev_join = nullptr, ev_prep = nullptr;
    if (!s_side) {
        cudaStreamCreateWithFlags(&s_side, cudaStreamNonBlocking);
        cudaEventCreateWithFlags(&ev_fork, cudaEventDisableTiming);
        cudaEventCreateWithFlags(&ev_join, cudaEventDisableTiming);
        cudaEventCreateWithFlags(&ev_prep, cudaEventDisableTiming);
    }

    // fork: weight pre-split + sort on the side stream (overlaps gemm_qkv tail)
    cudaEventRecord(ev_fork, 0);
    cudaStreamWaitEvent(s_side, ev_fork, 0);
    prep_weights<<<160, 256, 0, s_side>>>(Wq, Wk, Wv, W1, W2);
    cudaEventRecord(ev_prep, s_side);          // gemm_qkv needs split weights
    detect_kernel<<<1, 256, 0, s_side>>>((const unsigned int*)idx_kj, m);
    zero_hist<<<256, 256, 0, s_side>>>();
    hist_kernel<<<1024, 256, 0, s_side>>>(idx_ji, m);
    scan1_kernel<<<NBLK, 1024, 0, s_side>>>();
    scan2_kernel<<<1, 1, 0, s_side>>>();
    scan3_kernel<<<256, 256, 0, s_side>>>();
    scatter_kernel<<<1024, 256, 0, s_side>>>(idx_ji, idx_kj, m);
    cudaEventRecord(ev_join, s_side);

    // main stream: QKV projections (wait only for the weight pre-split)
    cudaStreamWaitEvent(0, ev_prep, 0);
    int gblocks = (nrows + 63) / 64;
    gemm_qkv<<<gblocks, 256, GEMM_SMEM>>>(feats, q_p, k_p, v_p, nrows);

    // join sort, then attention + fused MLP
    cudaStreamWaitEvent(0, ev_join, 0);
    int ablocks = (NROWS * 32 + 255) / 256;
    att_agg_kernel<<<ablocks, 256>>>();

    gemm_mlp<<<gblocks, 256, GEMM_SMEM>>>(b1, b2, v_p, out, nrows);
}